// round 11
// baseline (speedup 1.0000x reference)
#include <cuda_runtime.h>
#include <cuda_fp16.h>
#include <cstdint>

// VectorQuantizerRestart: z [16,128,4096] fp32, codebook [1024,128] fp32
#define D_DIM 128
#define T_DIM 4096
#define K_DIM 1024
#define N_TOK 65536

__device__ __align__(16) float g_cnorm[K_DIM];
// split-K candidates: [half 2][token]
__device__ float g_cv[2 * N_TOK];
__device__ int   g_ci[2 * N_TOK];
// fp16 2-limb codebook, fragment-ordered:
// [half2][chunk4][s8][limb2][ntp8][lane32][q4] uint32(f16x2)  (512 KB)
__device__ __align__(16) uint32_t g_bfrag[2 * 4 * 8 * 2 * 8 * 32 * 4];

__device__ __forceinline__ void split2(float x, unsigned short& h, unsigned short& m) {
    __half hh = __float2half_rn(x);
    float r = x - __half2float(hh);
    __half mm = __float2half_rn(r);
    h = __half_as_ushort(hh);
    m = __half_as_ushort(mm);
}

__device__ __forceinline__ void mma_f16(float* d, const uint32_t* a, const uint32_t* b) {
    asm volatile(
        "mma.sync.aligned.m16n8k16.row.col.f32.f16.f16.f32 "
        "{%0,%1,%2,%3}, {%4,%5,%6,%7}, {%8,%9}, {%0,%1,%2,%3};"
        : "+f"(d[0]), "+f"(d[1]), "+f"(d[2]), "+f"(d[3])
        : "r"(a[0]), "r"(a[1]), "r"(a[2]), "r"(a[3]), "r"(b[0]), "r"(b[1]));
}

// ---------------------------------------------------------------------------
// Kernel 1: codebook squared norms (one warp per code).
// ---------------------------------------------------------------------------
__global__ void vq_cnorm_kernel(const float* __restrict__ cb) {
    int w    = (blockIdx.x * blockDim.x + threadIdx.x) >> 5;
    int lane = threadIdx.x & 31;
    if (w >= K_DIM) return;
    float s = 0.f;
    #pragma unroll
    for (int d = lane; d < D_DIM; d += 32) {
        float v = cb[(size_t)w * D_DIM + d];
        s = fmaf(v, v, s);
    }
    #pragma unroll
    for (int o = 16; o > 0; o >>= 1) s += __shfl_xor_sync(0xffffffffu, s, o);
    if (lane == 0) g_cnorm[w] = s;
}

// ---------------------------------------------------------------------------
// Kernel 1b: split codebook into 2 fp16 limbs, fragment order for m16n8k16.
// e = [half][chunk][s][limb][ntp][lane][q]
// n = half*512 + chunk*128 + (ntp*2 + (q>>1))*8 + (lane>>2)
// k = s*16 + ((q&1)<<3) + (lane&3)*2
// ---------------------------------------------------------------------------
__global__ void vq_bfrag_kernel(const float* __restrict__ cb) {
    int e = blockIdx.x * blockDim.x + threadIdx.x;     // 131072
    int q    = e & 3;
    int lane = (e >> 2) & 31;
    int ntp  = (e >> 7) & 7;
    int limb = (e >> 10) & 1;
    int s    = (e >> 11) & 7;
    int chunk= (e >> 14) & 3;
    int half = (e >> 16) & 1;

    int n = half * 512 + chunk * 128 + (ntp * 2 + (q >> 1)) * 8 + (lane >> 2);
    int k = s * 16 + ((q & 1) << 3) + (lane & 3) * 2;
    float x0 = cb[n * D_DIM + k];
    float x1 = cb[n * D_DIM + k + 1];
    unsigned short h0, m0, h1, m1;
    split2(x0, h0, m0);
    split2(x1, h1, m1);
    unsigned short lo = (limb == 0) ? h0 : m0;
    unsigned short hi = (limb == 0) ? h1 : m1;
    g_bfrag[e] = (uint32_t)lo | ((uint32_t)hi << 16);
}

// ---------------------------------------------------------------------------
// Kernel 2: 3-term fp16 2-limb mma.sync + register argmin, split-K over codes.
// grid = 1024: blockIdx = tile*2 + half; each CTA = 512 codes in 4 chunks of 128.
// CTA: 256 thr = 8 warps = 4 mg x 2 ng; warp tile m32 x n64 (LDS-optimal shape:
// 393KB/chunk vs 655KB at m16n64 — crossbar now below the HMMA term).
// A (64KB) resident; B double-buffered (2 x 64KB), single-sync pipeline.
// ---------------------------------------------------------------------------
#define A_U4   4096            // uint4: [s8][mt8][limb2][lane32]
#define B_U4   4096            // per buffer: [s8][limb2][ntp8][lane32]
#define SMEM_BYTES ((A_U4 + 2 * B_U4) * 16 + 512 * 4)   // 198656

__global__ __launch_bounds__(256, 1)
void vq_argmin_kernel(const float* __restrict__ z) {
    extern __shared__ uint4 smem4[];
    uint4* As = smem4;
    uint4* Bs = smem4 + A_U4;
    float* cn = reinterpret_cast<float*>(smem4 + A_U4 + 2 * B_U4);

    const int tid  = threadIdx.x;
    const int lane = tid & 31;
    const int w    = tid >> 5;
    const int mg   = w >> 1;                 // 0..3  (m32 tile)
    const int ng   = w & 1;                  // 0..1  (n64 tile)

    const int tile = blockIdx.x >> 1;
    const int half = blockIdx.x & 1;
    const int n0 = tile * 128;
    const int kb0 = half * 512;
    const int bb = n0 >> 12;
    const int t0 = n0 & (T_DIM - 1);
    const float* zb = z + (size_t)bb * D_DIM * T_DIM + t0;

    const uint32_t bsm = (uint32_t)__cvta_generic_to_shared(Bs);
    const uint32_t cnsm = (uint32_t)__cvta_generic_to_shared(cn);
    const float4*  bsrc = reinterpret_cast<const float4*>(g_bfrag) + half * 4 * B_U4;

    // ---- group 0: cn (2KB) + B chunk 0 (64KB) — overlaps the A-split below
    if (tid < 128) {
        asm volatile("cp.async.ca.shared.global [%0], [%1], 16;"
                     :: "r"(cnsm + tid * 16u), "l"(g_cnorm + kb0 + tid * 4) : "memory");
    }
    #pragma unroll
    for (int i = 0; i < 16; ++i) {
        int e = i * 256 + tid;
        asm volatile("cp.async.cg.shared.global [%0], [%1], 16;"
                     :: "r"(bsm + (uint32_t)e * 16u), "l"(bsrc + e) : "memory");
    }
    asm volatile("cp.async.commit_group;" ::: "memory");

    // ---- A prologue: z -> 2 fp16 limbs in m16n8k16 fragment order.
    for (int p = w; p < 64; p += 8) {
        int s  = p >> 3;
        int mt = p & 7;
        int m = mt * 16 + (lane >> 2);
        int k = s * 16 + (lane & 3) * 2;
        float xv[8];
        xv[0] = zb[(k    ) * T_DIM + m    ];  xv[1] = zb[(k + 1) * T_DIM + m    ];
        xv[2] = zb[(k    ) * T_DIM + m + 8];  xv[3] = zb[(k + 1) * T_DIM + m + 8];
        xv[4] = zb[(k + 8) * T_DIM + m    ];  xv[5] = zb[(k + 9) * T_DIM + m    ];
        xv[6] = zb[(k + 8) * T_DIM + m + 8];  xv[7] = zb[(k + 9) * T_DIM + m + 8];
        unsigned short hh[8], mm[8];
        #pragma unroll
        for (int i = 0; i < 8; i++) split2(xv[i], hh[i], mm[i]);
        #pragma unroll
        for (int limb = 0; limb < 2; limb++) {
            const unsigned short* u = (limb == 0) ? hh : mm;
            uint4 v;
            v.x = (uint32_t)u[0] | ((uint32_t)u[1] << 16);
            v.y = (uint32_t)u[2] | ((uint32_t)u[3] << 16);
            v.z = (uint32_t)u[4] | ((uint32_t)u[5] << 16);
            v.w = (uint32_t)u[6] | ((uint32_t)u[7] << 16);
            As[((s * 8 + mt) * 2 + limb) * 32 + lane] = v;
        }
    }

    float minv[4];                            // [mt][row-half]
    int   mini[4];
    #pragma unroll
    for (int j = 0; j < 4; j++) { minv[j] = 3.4e38f; mini[j] = 0; }

    static const int TLA[3] = {0, 0, 1};
    static const int TLB[3] = {0, 1, 0};

    #pragma unroll 1
    for (int c = 0; c < 4; ++c) {
        asm volatile("cp.async.wait_group 0;" ::: "memory");
        __syncthreads();     // buf[c&1]+A(+cn) visible; all done reading buf[(c+1)&1]

        if (c < 3) {         // prefetch c+1 into the buffer just freed
            int buf1 = (c + 1) & 1;
            const float4* src = bsrc + (c + 1) * B_U4;
            #pragma unroll
            for (int i = 0; i < 16; ++i) {
                int e = i * 256 + tid;
                asm volatile("cp.async.cg.shared.global [%0], [%1], 16;"
                             :: "r"(bsm + (uint32_t)(buf1 * B_U4 + e) * 16u),
                                "l"(src + e) : "memory");
            }
            asm volatile("cp.async.commit_group;" ::: "memory");
        }

        const uint4* Bb = Bs + (c & 1) * B_U4;
        float acc[2][8][4];                   // [mt][ntile][quad]
        #pragma unroll
        for (int mt = 0; mt < 2; mt++)
            #pragma unroll
            for (int nt = 0; nt < 8; nt++)
                #pragma unroll
                for (int qi = 0; qi < 4; qi++) acc[mt][nt][qi] = 0.f;

        #pragma unroll
        for (int s = 0; s < 8; ++s) {
            uint32_t afr[2][2][4];            // [mt][limb][4]
            #pragma unroll
            for (int mt = 0; mt < 2; mt++)
                #pragma unroll
                for (int limb = 0; limb < 2; limb++) {
                    uint4 v = As[((s * 8 + mg * 2 + mt) * 2 + limb) * 32 + lane];
                    afr[mt][limb][0] = v.x; afr[mt][limb][1] = v.y;
                    afr[mt][limb][2] = v.z; afr[mt][limb][3] = v.w;
                }
            uint32_t bfr[2][8][2];            // [limb][ntile][2 regs]
            #pragma unroll
            for (int limb = 0; limb < 2; limb++)
                #pragma unroll
                for (int np = 0; np < 4; np++) {
                    uint4 v = Bb[((s * 2 + limb) * 8 + ng * 4 + np) * 32 + lane];
                    bfr[limb][np * 2    ][0] = v.x; bfr[limb][np * 2    ][1] = v.y;
                    bfr[limb][np * 2 + 1][0] = v.z; bfr[limb][np * 2 + 1][1] = v.w;
                }
            // 3 terms: h*h, h*m, m*h (m*m ~ 2^-22 rel: negligible)
            #pragma unroll
            for (int term = 0; term < 3; term++) {
                const int la = TLA[term], lb = TLB[term];
                #pragma unroll
                for (int nt = 0; nt < 8; nt++)
                    #pragma unroll
                    for (int mt = 0; mt < 2; mt++)
                        mma_f16(acc[mt][nt], afr[mt][la], bfr[lb][nt]);
            }
        }

        // ---- epilogue: d2 = ||c||^2 - 2*dot, strict-< running min (n ascending)
        #pragma unroll
        for (int nt = 0; nt < 8; nt++) {
            int nl = c * 128 + ng * 64 + nt * 8 + 2 * (lane & 3);
            float cv0 = cn[nl], cv1 = cn[nl + 1];
            int n = kb0 + nl;
            #pragma unroll
            for (int mt = 0; mt < 2; mt++) {
                float d00 = fmaf(-2.f, acc[mt][nt][0], cv0);
                float d01 = fmaf(-2.f, acc[mt][nt][1], cv1);
                float d10 = fmaf(-2.f, acc[mt][nt][2], cv0);
                float d11 = fmaf(-2.f, acc[mt][nt][3], cv1);
                int j0 = mt * 2, j1 = mt * 2 + 1;
                if (d00 < minv[j0]) { minv[j0] = d00; mini[j0] = n; }
                if (d01 < minv[j0]) { minv[j0] = d01; mini[j0] = n + 1; }
                if (d10 < minv[j1]) { minv[j1] = d10; mini[j1] = n; }
                if (d11 < minv[j1]) { minv[j1] = d11; mini[j1] = n + 1; }
            }
        }
    }

    // ---- cross-thread reduce: 8 candidates per token -> g_cv/g_ci[half]
    __syncthreads();                          // all compute done before smem reuse
    float* rv = reinterpret_cast<float*>(smem4);          // [128][8]
    int*   ri = reinterpret_cast<int*>(rv + 1024);
    #pragma unroll
    for (int mt = 0; mt < 2; mt++)
        #pragma unroll
        for (int rh = 0; rh < 2; rh++) {
            int tok  = mg * 32 + mt * 16 + rh * 8 + (lane >> 2);
            int slot = ng * 4 + (lane & 3);
            rv[tok * 8 + slot] = minv[mt * 2 + rh];
            ri[tok * 8 + slot] = mini[mt * 2 + rh];
        }
    __syncthreads();
    if (tid < 128) {
        float bv = rv[tid * 8];
        int   bi = ri[tid * 8];
        #pragma unroll
        for (int x = 1; x < 8; x++) {
            float v = rv[tid * 8 + x];
            int   k = ri[tid * 8 + x];
            if (v < bv || (v == bv && k < bi)) { bv = v; bi = k; }
        }
        g_cv[half * N_TOK + n0 + tid] = bv;
        g_ci[half * N_TOK + n0 + tid] = bi;
    }
}

// ---------------------------------------------------------------------------
// Kernel 3: gather + split-K merge. Warp = 32 consecutive t, 8-wide d slice.
// half0 indices < half1, so half0 wins ties (first-min semantics).
// ---------------------------------------------------------------------------
__global__ void vq_gather_kernel(const float* __restrict__ cb, float* __restrict__ out) {
    int gw   = (blockIdx.x * blockDim.x + threadIdx.x) >> 5;   // 32768 warps
    int lane = threadIdx.x & 31;
    int t  = ((gw & 127) << 5) + lane;
    int d0 = ((gw >> 7) & 15) << 3;
    int b  = gw >> 11;
    int tg = b * T_DIM + t;
    float v0 = g_cv[tg], v1 = g_cv[N_TOK + tg];
    int idx = (v1 < v0) ? g_ci[N_TOK + tg] : g_ci[tg];
    const float4* src = reinterpret_cast<const float4*>(cb + (size_t)idx * D_DIM + d0);
    float4 w0 = __ldg(src);
    float4 w1 = __ldg(src + 1);
    size_t obase = ((size_t)b * D_DIM + d0) * T_DIM + t;
    out[obase + 0 * T_DIM] = w0.x;
    out[obase + 1 * T_DIM] = w0.y;
    out[obase + 2 * T_DIM] = w0.z;
    out[obase + 3 * T_DIM] = w0.w;
    out[obase + 4 * T_DIM] = w1.x;
    out[obase + 5 * T_DIM] = w1.y;
    out[obase + 6 * T_DIM] = w1.z;
    out[obase + 7 * T_DIM] = w1.w;
}

// ---------------------------------------------------------------------------
extern "C" void kernel_launch(void* const* d_in, const int* in_sizes, int n_in,
                              void* d_out, int out_size) {
    const float* z  = (const float*)d_in[0];
    const float* cb = (const float*)d_in[1];
    float* out = (float*)d_out;

    cudaFuncSetAttribute(vq_argmin_kernel,
                         cudaFuncAttributeMaxDynamicSharedMemorySize, SMEM_BYTES);

    vq_cnorm_kernel<<<K_DIM / 8, 256>>>(cb);
    vq_bfrag_kernel<<<512, 256>>>(cb);
    vq_argmin_kernel<<<(N_TOK / 128) * 2, 256, SMEM_BYTES>>>(z);
    vq_gather_kernel<<<4096, 256>>>(cb, out);
}

// round 12
// speedup vs baseline: 1.0158x; 1.0158x over previous
#include <cuda_runtime.h>
#include <cuda_fp16.h>
#include <cstdint>

// VectorQuantizerRestart: z [16,128,4096] fp32, codebook [1024,128] fp32
#define D_DIM 128
#define T_DIM 4096
#define K_DIM 1024
#define N_TOK 65536

__device__ __align__(16) float g_cnorm[K_DIM];
// split-K candidates: [half 2][token]
__device__ float g_cv[2 * N_TOK];
__device__ int   g_ci[2 * N_TOK];
// fp16 2-limb codebook, fragment-ordered:
// [half2][chunk4][s8][limb2][ntp8][lane32][q4] uint32(f16x2)  (512 KB)
__device__ __align__(16) uint32_t g_bfrag[2 * 4 * 8 * 2 * 8 * 32 * 4];

__device__ __forceinline__ void split2(float x, unsigned short& h, unsigned short& m) {
    __half hh = __float2half_rn(x);
    float r = x - __half2float(hh);
    __half mm = __float2half_rn(r);
    h = __half_as_ushort(hh);
    m = __half_as_ushort(mm);
}

__device__ __forceinline__ void mma_f16(float* d, const uint32_t* a, const uint32_t* b) {
    asm volatile(
        "mma.sync.aligned.m16n8k16.row.col.f32.f16.f16.f32 "
        "{%0,%1,%2,%3}, {%4,%5,%6,%7}, {%8,%9}, {%0,%1,%2,%3};"
        : "+f"(d[0]), "+f"(d[1]), "+f"(d[2]), "+f"(d[3])
        : "r"(a[0]), "r"(a[1]), "r"(a[2]), "r"(a[3]), "r"(b[0]), "r"(b[1]));
}

// ---------------------------------------------------------------------------
// Kernel 1: codebook squared norms (one warp per code).
// ---------------------------------------------------------------------------
__global__ void vq_cnorm_kernel(const float* __restrict__ cb) {
    int w    = (blockIdx.x * blockDim.x + threadIdx.x) >> 5;
    int lane = threadIdx.x & 31;
    if (w >= K_DIM) return;
    float s = 0.f;
    #pragma unroll
    for (int d = lane; d < D_DIM; d += 32) {
        float v = cb[(size_t)w * D_DIM + d];
        s = fmaf(v, v, s);
    }
    #pragma unroll
    for (int o = 16; o > 0; o >>= 1) s += __shfl_xor_sync(0xffffffffu, s, o);
    if (lane == 0) g_cnorm[w] = s;
}

// ---------------------------------------------------------------------------
// Kernel 1b: split codebook into 2 fp16 limbs, fragment order for m16n8k16.
// e = [half][chunk][s][limb][ntp][lane][q]
// n = half*512 + chunk*128 + (ntp*2 + (q>>1))*8 + (lane>>2)
// k = s*16 + ((q&1)<<3) + (lane&3)*2
// ---------------------------------------------------------------------------
__global__ void vq_bfrag_kernel(const float* __restrict__ cb) {
    int e = blockIdx.x * blockDim.x + threadIdx.x;     // 131072
    int q    = e & 3;
    int lane = (e >> 2) & 31;
    int ntp  = (e >> 7) & 7;
    int limb = (e >> 10) & 1;
    int s    = (e >> 11) & 7;
    int chunk= (e >> 14) & 3;
    int half = (e >> 16) & 1;

    int n = half * 512 + chunk * 128 + (ntp * 2 + (q >> 1)) * 8 + (lane >> 2);
    int k = s * 16 + ((q & 1) << 3) + (lane & 3) * 2;
    float x0 = cb[n * D_DIM + k];
    float x1 = cb[n * D_DIM + k + 1];
    unsigned short h0, m0, h1, m1;
    split2(x0, h0, m0);
    split2(x1, h1, m1);
    unsigned short lo = (limb == 0) ? h0 : m0;
    unsigned short hi = (limb == 0) ? h1 : m1;
    g_bfrag[e] = (uint32_t)lo | ((uint32_t)hi << 16);
}

// ---------------------------------------------------------------------------
// Kernel 2: 3-term fp16 2-limb mma.sync + register argmin, split-K over codes.
// grid = 1024: blockIdx = tile*2 + half; each CTA = 512 codes in 4 chunks of 128.
// CTA: 512 thr = 16 warps = 4 mg x 4 ng (4 warps/SMSP); warp tile m32 x n32:
// keeps R10's TLP (R11 showed 2 warps/SMSP loses to LDS savings) while cutting
// LDS/chunk 655KB -> 524KB.
// A (64KB) resident; B double-buffered (2 x 64KB), single-sync pipeline.
// ---------------------------------------------------------------------------
#define A_U4   4096            // uint4: [s8][mt8][limb2][lane32]
#define B_U4   4096            // per buffer: [s8][limb2][ntp8][lane32]
#define SMEM_BYTES ((A_U4 + 2 * B_U4) * 16 + 512 * 4)   // 198656

__global__ __launch_bounds__(512, 1)
void vq_argmin_kernel(const float* __restrict__ z) {
    extern __shared__ uint4 smem4[];
    uint4* As = smem4;
    uint4* Bs = smem4 + A_U4;
    float* cn = reinterpret_cast<float*>(smem4 + A_U4 + 2 * B_U4);

    const int tid  = threadIdx.x;
    const int lane = tid & 31;
    const int w    = tid >> 5;
    const int mg   = w >> 2;                 // 0..3  (m32 tile)
    const int ng   = w & 3;                  // 0..3  (n32 tile)

    const int tile = blockIdx.x >> 1;
    const int half = blockIdx.x & 1;
    const int n0 = tile * 128;
    const int kb0 = half * 512;
    const int bb = n0 >> 12;
    const int t0 = n0 & (T_DIM - 1);
    const float* zb = z + (size_t)bb * D_DIM * T_DIM + t0;

    const uint32_t bsm = (uint32_t)__cvta_generic_to_shared(Bs);
    const uint32_t cnsm = (uint32_t)__cvta_generic_to_shared(cn);
    const float4*  bsrc = reinterpret_cast<const float4*>(g_bfrag) + half * 4 * B_U4;

    // ---- group 0: cn (2KB) + B chunk 0 (64KB) — overlaps the A-split below
    if (tid < 128) {
        asm volatile("cp.async.ca.shared.global [%0], [%1], 16;"
                     :: "r"(cnsm + tid * 16u), "l"(g_cnorm + kb0 + tid * 4) : "memory");
    }
    #pragma unroll
    for (int i = 0; i < 8; ++i) {
        int e = i * 512 + tid;
        asm volatile("cp.async.cg.shared.global [%0], [%1], 16;"
                     :: "r"(bsm + (uint32_t)e * 16u), "l"(bsrc + e) : "memory");
    }
    asm volatile("cp.async.commit_group;" ::: "memory");

    // ---- A prologue: z -> 2 fp16 limbs in m16n8k16 fragment order.
    for (int p = w; p < 64; p += 16) {
        int s  = p >> 3;
        int mt = p & 7;
        int m = mt * 16 + (lane >> 2);
        int k = s * 16 + (lane & 3) * 2;
        float xv[8];
        xv[0] = zb[(k    ) * T_DIM + m    ];  xv[1] = zb[(k + 1) * T_DIM + m    ];
        xv[2] = zb[(k    ) * T_DIM + m + 8];  xv[3] = zb[(k + 1) * T_DIM + m + 8];
        xv[4] = zb[(k + 8) * T_DIM + m    ];  xv[5] = zb[(k + 9) * T_DIM + m    ];
        xv[6] = zb[(k + 8) * T_DIM + m + 8];  xv[7] = zb[(k + 9) * T_DIM + m + 8];
        unsigned short hh[8], mm[8];
        #pragma unroll
        for (int i = 0; i < 8; i++) split2(xv[i], hh[i], mm[i]);
        #pragma unroll
        for (int limb = 0; limb < 2; limb++) {
            const unsigned short* u = (limb == 0) ? hh : mm;
            uint4 v;
            v.x = (uint32_t)u[0] | ((uint32_t)u[1] << 16);
            v.y = (uint32_t)u[2] | ((uint32_t)u[3] << 16);
            v.z = (uint32_t)u[4] | ((uint32_t)u[5] << 16);
            v.w = (uint32_t)u[6] | ((uint32_t)u[7] << 16);
            As[((s * 8 + mt) * 2 + limb) * 32 + lane] = v;
        }
    }

    float minv[4];                            // [mt][row-half]
    int   mini[4];
    #pragma unroll
    for (int j = 0; j < 4; j++) { minv[j] = 3.4e38f; mini[j] = 0; }

    static const int TLA[3] = {0, 0, 1};
    static const int TLB[3] = {0, 1, 0};

    #pragma unroll 1
    for (int c = 0; c < 4; ++c) {
        asm volatile("cp.async.wait_group 0;" ::: "memory");
        __syncthreads();     // buf[c&1]+A(+cn) visible; all done reading buf[(c+1)&1]

        if (c < 3) {         // prefetch c+1 into the buffer just freed
            int buf1 = (c + 1) & 1;
            const float4* src = bsrc + (c + 1) * B_U4;
            #pragma unroll
            for (int i = 0; i < 8; ++i) {
                int e = i * 512 + tid;
                asm volatile("cp.async.cg.shared.global [%0], [%1], 16;"
                             :: "r"(bsm + (uint32_t)(buf1 * B_U4 + e) * 16u),
                                "l"(src + e) : "memory");
            }
            asm volatile("cp.async.commit_group;" ::: "memory");
        }

        const uint4* Bb = Bs + (c & 1) * B_U4;
        float acc[2][4][4];                   // [mt][ntile][quad]
        #pragma unroll
        for (int mt = 0; mt < 2; mt++)
            #pragma unroll
            for (int nt = 0; nt < 4; nt++)
                #pragma unroll
                for (int qi = 0; qi < 4; qi++) acc[mt][nt][qi] = 0.f;

        #pragma unroll
        for (int s = 0; s < 8; ++s) {
            uint32_t afr[2][2][4];            // [mt][limb][4]
            #pragma unroll
            for (int mt = 0; mt < 2; mt++)
                #pragma unroll
                for (int limb = 0; limb < 2; limb++) {
                    uint4 v = As[((s * 8 + mg * 2 + mt) * 2 + limb) * 32 + lane];
                    afr[mt][limb][0] = v.x; afr[mt][limb][1] = v.y;
                    afr[mt][limb][2] = v.z; afr[mt][limb][3] = v.w;
                }
            uint32_t bfr[2][4][2];            // [limb][ntile][2 regs]
            #pragma unroll
            for (int limb = 0; limb < 2; limb++)
                #pragma unroll
                for (int np = 0; np < 2; np++) {
                    uint4 v = Bb[((s * 2 + limb) * 8 + ng * 2 + np) * 32 + lane];
                    bfr[limb][np * 2    ][0] = v.x; bfr[limb][np * 2    ][1] = v.y;
                    bfr[limb][np * 2 + 1][0] = v.z; bfr[limb][np * 2 + 1][1] = v.w;
                }
            // 3 terms: h*h, h*m, m*h (m*m ~ 2^-22 rel: negligible)
            #pragma unroll
            for (int term = 0; term < 3; term++) {
                const int la = TLA[term], lb = TLB[term];
                #pragma unroll
                for (int nt = 0; nt < 4; nt++)
                    #pragma unroll
                    for (int mt = 0; mt < 2; mt++)
                        mma_f16(acc[mt][nt], afr[mt][la], bfr[lb][nt]);
            }
        }

        // ---- epilogue: d2 = ||c||^2 - 2*dot, strict-< running min (n ascending)
        #pragma unroll
        for (int nt = 0; nt < 4; nt++) {
            int nl = c * 128 + ng * 32 + nt * 8 + 2 * (lane & 3);
            float cv0 = cn[nl], cv1 = cn[nl + 1];
            int n = kb0 + nl;
            #pragma unroll
            for (int mt = 0; mt < 2; mt++) {
                float d00 = fmaf(-2.f, acc[mt][nt][0], cv0);
                float d01 = fmaf(-2.f, acc[mt][nt][1], cv1);
                float d10 = fmaf(-2.f, acc[mt][nt][2], cv0);
                float d11 = fmaf(-2.f, acc[mt][nt][3], cv1);
                int j0 = mt * 2, j1 = mt * 2 + 1;
                if (d00 < minv[j0]) { minv[j0] = d00; mini[j0] = n; }
                if (d01 < minv[j0]) { minv[j0] = d01; mini[j0] = n + 1; }
                if (d10 < minv[j1]) { minv[j1] = d10; mini[j1] = n; }
                if (d11 < minv[j1]) { minv[j1] = d11; mini[j1] = n + 1; }
            }
        }
    }

    // ---- cross-thread reduce: 16 candidates per token -> g_cv/g_ci[half]
    __syncthreads();                          // all compute done before smem reuse
    float* rv = reinterpret_cast<float*>(smem4);          // [128][16]
    int*   ri = reinterpret_cast<int*>(rv + 2048);
    #pragma unroll
    for (int mt = 0; mt < 2; mt++)
        #pragma unroll
        for (int rh = 0; rh < 2; rh++) {
            int tok  = mg * 32 + mt * 16 + rh * 8 + (lane >> 2);
            int slot = ng * 4 + (lane & 3);
            rv[tok * 16 + slot] = minv[mt * 2 + rh];
            ri[tok * 16 + slot] = mini[mt * 2 + rh];
        }
    __syncthreads();
    if (tid < 128) {
        float bv = rv[tid * 16];
        int   bi = ri[tid * 16];
        #pragma unroll
        for (int x = 1; x < 16; x++) {
            float v = rv[tid * 16 + x];
            int   k = ri[tid * 16 + x];
            if (v < bv || (v == bv && k < bi)) { bv = v; bi = k; }
        }
        g_cv[half * N_TOK + n0 + tid] = bv;
        g_ci[half * N_TOK + n0 + tid] = bi;
    }
}

// ---------------------------------------------------------------------------
// Kernel 3: gather + split-K merge. Warp = 32 consecutive t, 8-wide d slice.
// half0 indices < half1, so half0 wins ties (first-min semantics).
// ---------------------------------------------------------------------------
__global__ void vq_gather_kernel(const float* __restrict__ cb, float* __restrict__ out) {
    int gw   = (blockIdx.x * blockDim.x + threadIdx.x) >> 5;   // 32768 warps
    int lane = threadIdx.x & 31;
    int t  = ((gw & 127) << 5) + lane;
    int d0 = ((gw >> 7) & 15) << 3;
    int b  = gw >> 11;
    int tg = b * T_DIM + t;
    float v0 = g_cv[tg], v1 = g_cv[N_TOK + tg];
    int idx = (v1 < v0) ? g_ci[N_TOK + tg] : g_ci[tg];
    const float4* src = reinterpret_cast<const float4*>(cb + (size_t)idx * D_DIM + d0);
    float4 w0 = __ldg(src);
    float4 w1 = __ldg(src + 1);
    size_t obase = ((size_t)b * D_DIM + d0) * T_DIM + t;
    out[obase + 0 * T_DIM] = w0.x;
    out[obase + 1 * T_DIM] = w0.y;
    out[obase + 2 * T_DIM] = w0.z;
    out[obase + 3 * T_DIM] = w0.w;
    out[obase + 4 * T_DIM] = w1.x;
    out[obase + 5 * T_DIM] = w1.y;
    out[obase + 6 * T_DIM] = w1.z;
    out[obase + 7 * T_DIM] = w1.w;
}

// ---------------------------------------------------------------------------
extern "C" void kernel_launch(void* const* d_in, const int* in_sizes, int n_in,
                              void* d_out, int out_size) {
    const float* z  = (const float*)d_in[0];
    const float* cb = (const float*)d_in[1];
    float* out = (float*)d_out;

    cudaFuncSetAttribute(vq_argmin_kernel,
                         cudaFuncAttributeMaxDynamicSharedMemorySize, SMEM_BYTES);

    vq_cnorm_kernel<<<K_DIM / 8, 256>>>(cb);
    vq_bfrag_kernel<<<512, 256>>>(cb);
    vq_argmin_kernel<<<(N_TOK / 128) * 2, 512, SMEM_BYTES>>>(z);
    vq_gather_kernel<<<4096, 256>>>(cb, out);
}